// round 13
// baseline (speedup 1.0000x reference)
#include <cuda_runtime.h>
#include <cuda_bf16.h>
#include <cstdint>

#define N_ROWS_U 16384
#define RANK     64
#define N_COLS_B 4096
#define KCB      2048
#define DS       16
#define SUBS_U   65536
#define SUBS_B   16384
#define TOTAL_SUBS 81920
#define KE 192
#define NUNITS   (TOTAL_SUBS / 16)    // 5120
#define NGROUPS  1707                 // ceil(5120/3)
#define NWARPTOT (148 * 12)           // 1776

__device__ __align__(16) unsigned short g_Aext[(size_t)N_ROWS_U * KE];
__device__ __align__(16) unsigned short g_Bext[(size_t)N_COLS_B * KE];
__device__ __align__(16) unsigned short g_Ghi [(size_t)TOTAL_SUBS * 16]; // hi only
__device__ __align__(16) unsigned short g_Chi [(size_t)KCB * 16];        // hi only
__device__ float g_CbBias[KCB];

// ---- exact fp32 chains (selection identity; unchanged since R7) ----
__device__ __forceinline__ float bias_of(const float* row) {
    float n = row[0] * row[0];
    #pragma unroll
    for (int i = 1; i < DS; ++i) n = fmaf(row[i], row[i], n);
    return -0.5f * n;
}
__device__ __forceinline__ float score_of(const float* g, const float* row, float bias) {
    float A = bias, B = 0.0f;
    #pragma unroll
    for (int j = 0; j < 8; ++j) {
        A = fmaf(g[2 * j],     row[2 * j],     A);
        B = fmaf(g[2 * j + 1], row[2 * j + 1], B);
    }
    return A + B;
}
__device__ __noinline__ float exact_for(int s, int c,
    const float* __restrict__ U, const float* __restrict__ Bm,
    const float* __restrict__ rsU, const float* __restrict__ rsB,
    const float* __restrict__ cb)
{
    const float* W; float rs;
    if (s < SUBS_U) { W = U + (size_t)s * DS; rs = rsU[s >> 2]; }
    else { int t = s - SUBS_U; W = Bm + (size_t)t * DS; rs = rsB[t >> 8]; }
    const float inv = 1.0f / rs;
    float g[DS];
    const float4* w4 = (const float4*)W;
    #pragma unroll
    for (int q = 0; q < 4; ++q) {
        float4 v = w4[q];
        g[4*q+0] = v.x * inv; g[4*q+1] = v.y * inv;
        g[4*q+2] = v.z * inv; g[4*q+3] = v.w * inv;
    }
    const float* row = cb + (size_t)c * DS;
    return score_of(g, row, bias_of(row));
}

__device__ __forceinline__ uint32_t smem_u32(const void* p) {
    uint32_t a;
    asm("{ .reg .u64 t; cvta.to.shared.u64 t, %1; cvt.u32.u64 %0, t; }"
        : "=r"(a) : "l"(p));
    return a;
}
__device__ __forceinline__ void ldsm4(uint32_t& r0, uint32_t& r1,
                                      uint32_t& r2, uint32_t& r3, uint32_t addr) {
    asm volatile("ldmatrix.sync.aligned.m8n8.x4.shared.b16 {%0,%1,%2,%3}, [%4];"
                 : "=r"(r0), "=r"(r1), "=r"(r2), "=r"(r3) : "r"(addr));
}
__device__ __forceinline__ void mma16816(float* c, const uint32_t* a,
                                         uint32_t b0, uint32_t b1) {
    asm("mma.sync.aligned.m16n8k16.row.col.f32.bf16.bf16.f32 "
        "{%0,%1,%2,%3}, {%4,%5,%6,%7}, {%8,%9}, {%0,%1,%2,%3};"
        : "+f"(c[0]), "+f"(c[1]), "+f"(c[2]), "+f"(c[3])
        : "r"(a[0]), "r"(a[1]), "r"(a[2]), "r"(a[3]), "r"(b0), "r"(b1));
}
__device__ __forceinline__ void mma16816z(float* c, const uint32_t* a,
                                          uint32_t b0, uint32_t b1) {
    float z = 0.0f;
    asm("mma.sync.aligned.m16n8k16.row.col.f32.bf16.bf16.f32 "
        "{%0,%1,%2,%3}, {%4,%5,%6,%7}, {%8,%9}, {%10,%11,%12,%13};"
        : "=f"(c[0]), "=f"(c[1]), "=f"(c[2]), "=f"(c[3])
        : "r"(a[0]), "r"(a[1]), "r"(a[2]), "r"(a[3]), "r"(b0), "r"(b1),
          "f"(z), "f"(z), "f"(z), "f"(z));
}
__device__ __forceinline__ float2 b2f2(uint32_t v) {
    __nv_bfloat162 h = *reinterpret_cast<__nv_bfloat162*>(&v);
    return __bfloat1622float2(h);
}

// ---- prep: codebook bf16 hi image + fp32 bias ----
__global__ __launch_bounds__(128) void prep_cb(const float* __restrict__ cb) {
    const int c = blockIdx.x * 128 + threadIdx.x;
    float row[DS];
    const float4* r4 = (const float4*)(cb + (size_t)c * DS);
    #pragma unroll
    for (int q = 0; q < 4; ++q) {
        float4 v = r4[q];
        row[4*q] = v.x; row[4*q+1] = v.y; row[4*q+2] = v.z; row[4*q+3] = v.w;
    }
    g_CbBias[c] = bias_of(row);
    unsigned short* o = g_Chi + (size_t)c * 16;
    #pragma unroll
    for (int i = 0; i < DS; ++i)
        o[i] = __bfloat16_as_ushort(__float2bfloat16(row[i]));
}

// ---- prep: subvector bf16 hi image ----
__global__ __launch_bounds__(128) void prep_g(
    const float* __restrict__ U, const float* __restrict__ Bm,
    const float* __restrict__ rsU, const float* __restrict__ rsB)
{
    const int s = blockIdx.x * 128 + threadIdx.x;
    const float* W; float rsv;
    if (s < SUBS_U) { W = U + (size_t)s * DS; rsv = rsU[s >> 2]; }
    else { int s2 = s - SUBS_U; W = Bm + (size_t)s2 * DS; rsv = rsB[s2 >> 8]; }
    const float inv = 1.0f / rsv;
    unsigned short* o = g_Ghi + (size_t)s * 16;
    const float4* w4 = (const float4*)W;
    #pragma unroll
    for (int q = 0; q < 4; ++q) {
        float4 v = w4[q];
        float gg[4] = {v.x * inv, v.y * inv, v.z * inv, v.w * inv};
        #pragma unroll
        for (int e = 0; e < 4; ++e)
            o[4*q + e] = __bfloat16_as_ushort(__float2bfloat16(gg[e]));
    }
}

// ---- stage one selected codeword into split-bf16 GEMM operands ----
__device__ __noinline__ void stage_row(int s, int bidx,
    const float* __restrict__ rsU, const float* __restrict__ rsB,
    const float* __restrict__ cb)
{
    float rsv = (s < SUBS_U) ? rsU[s >> 2] : rsB[(s - SUBS_U) >> 8];
    float cw[DS];
    const float4* c4 = (const float4*)(cb + (size_t)bidx * DS);
    #pragma unroll
    for (int q = 0; q < 4; ++q) {
        float4 v = c4[q];
        cw[4*q+0] = v.x * rsv; cw[4*q+1] = v.y * rsv;
        cw[4*q+2] = v.z * rsv; cw[4*q+3] = v.w * rsv;
    }
    if (s < SUBS_U) {
        const int m = s >> 2, kk0 = (s & 3) << 4;
        unsigned short* rowp = g_Aext + (size_t)m * KE;
        #pragma unroll
        for (int e = 0; e < 8; ++e) {
            const int k = kk0 + 2 * e;
            float x0 = cw[2*e], x1 = cw[2*e+1];
            __nv_bfloat16 h0 = __float2bfloat16(x0), h1 = __float2bfloat16(x1);
            __nv_bfloat16 l0 = __float2bfloat16(x0 - __bfloat162float(h0));
            __nv_bfloat16 l1 = __float2bfloat16(x1 - __bfloat162float(h1));
            unsigned hp = (unsigned)__bfloat16_as_ushort(h0)
                        | ((unsigned)__bfloat16_as_ushort(h1) << 16);
            unsigned lp = (unsigned)__bfloat16_as_ushort(l0)
                        | ((unsigned)__bfloat16_as_ushort(l1) << 16);
            *(unsigned*)(rowp + k)       = hp;
            *(unsigned*)(rowp + 64 + k)  = lp;
            *(unsigned*)(rowp + 128 + k) = hp;
        }
    } else {
        const int s2 = s - SUBS_U, kB = s2 >> 8, n0g = (s2 & 255) << 4;
        #pragma unroll
        for (int i = 0; i < DS; ++i) {
            unsigned short* rowp = g_Bext + (size_t)(n0g + i) * KE;
            float x = cw[i];
            __nv_bfloat16 h = __float2bfloat16(x);
            __nv_bfloat16 l = __float2bfloat16(x - __bfloat162float(h));
            rowp[kB]       = __bfloat16_as_ushort(h);
            rowp[64 + kB]  = __bfloat16_as_ushort(h);
            rowp[128 + kB] = __bfloat16_as_ushort(l);
        }
    }
}

// ---------------------------------------------------------------------------
// Score kernel: K=16 one-sided bf16 rank + exact fp32 verify.
// 148 CTAs x 12 warps; each warp: 3 row-sets of 16 rows sharing B loads.
// Codebook resident in smem: 2048 rows x 32 B at pitch 48 (conflict-free).
// ---------------------------------------------------------------------------
#define QPI 48
#define Q_CB (KCB * QPI)              // 98304
#define Q_SMEM (Q_CB + KCB * 4)       // 106496

__global__ __launch_bounds__(384) void score_kernel(
    const float* __restrict__ U, const float* __restrict__ Bm,
    const float* __restrict__ rsU, const float* __restrict__ rsB,
    const float* __restrict__ cb)
{
    extern __shared__ __align__(16) unsigned char qsm[];
    float* sBias = (float*)(qsm + Q_CB);
    const int tid = threadIdx.x, wid = tid >> 5, lane = tid & 31;

    {   // stage C (2048 rows x 2 uint4, pitch 48) + bias
        const uint4* src = (const uint4*)g_Chi;
        for (int idx = tid; idx < KCB * 2; idx += 384) {
            const int r = idx >> 1, j = idx & 1;
            *(uint4*)(qsm + r * QPI + j * 16) = src[idx];
        }
        for (int c = tid; c < KCB; c += 384) sBias[c] = g_CbBias[c];
    }
    __syncthreads();

    const uint32_t sbase = smem_u32(qsm);
    const int g8 = lane >> 3;
    const int bRow = ((g8 & 2) ? 8 : 0) + (lane & 7);
    const int bKof = (g8 & 1) * 16;
    const int lq = lane >> 2, lr = lane & 3, cp = lr * 2;

    const int group = blockIdx.x * 12 + wid;
    for (int gg = group; gg < NGROUPS; gg += NWARPTOT) {
        int  su[3]; bool val[3];
        uint32_t a[3][4];
        float tol0[3], tol1[3];

        #pragma unroll
        for (int j = 0; j < 3; ++j) {
            const int u = 3 * gg + j;
            val[j] = (u < NUNITS);
            const int uc = val[j] ? u : 0;
            su[j] = uc * 16;
            const int s0 = su[j] + lq, s1 = s0 + 8;
            const unsigned* G = (const unsigned*)g_Ghi;
            a[j][0] = G[(size_t)s0 * 8 + lr];
            a[j][1] = G[(size_t)s1 * 8 + lr];
            a[j][2] = G[(size_t)s0 * 8 + 4 + lr];
            a[j][3] = G[(size_t)s1 * 8 + 4 + lr];
            // tol from hi-norm (quad holds 4x4 elems of each row)
            float2 f0a = b2f2(a[j][0]), f0b = b2f2(a[j][2]);
            float2 f1a = b2f2(a[j][1]), f1b = b2f2(a[j][3]);
            float p0 = f0a.x*f0a.x + f0a.y*f0a.y + f0b.x*f0b.x + f0b.y*f0b.y;
            float p1 = f1a.x*f1a.x + f1a.y*f1a.y + f1b.x*f1b.x + f1b.y*f1b.y;
            p0 += __shfl_xor_sync(~0u, p0, 1); p0 += __shfl_xor_sync(~0u, p0, 2);
            p1 += __shfl_xor_sync(~0u, p1, 1); p1 += __shfl_xor_sync(~0u, p1, 2);
            tol0[j] = 2.02e-3f * sqrtf(p0);
            tol1[j] = 2.02e-3f * sqrtf(p1);
        }

        // ---- pass 1: ranked row maxima ----
        float r0[3] = {-3.402823466e38f, -3.402823466e38f, -3.402823466e38f};
        float r1[3] = {-3.402823466e38f, -3.402823466e38f, -3.402823466e38f};
        for (int ch = 0; ch < 32; ++ch) {
            uint32_t b[4][4];
            #pragma unroll
            for (int bt = 0; bt < 4; ++bt)
                ldsm4(b[bt][0], b[bt][1], b[bt][2], b[bt][3],
                      sbase + (uint32_t)((ch * 64 + bt * 16 + bRow) * QPI + bKof));
            #pragma unroll
            for (int j = 0; j < 3; ++j) {
                float acc[8][4];
                #pragma unroll
                for (int nt = 0; nt < 8; ++nt)
                    mma16816z(acc[nt], a[j], b[nt>>1][(nt&1)*2], b[nt>>1][(nt&1)*2+1]);
                #pragma unroll
                for (int nt = 0; nt < 8; ++nt) {
                    float2 bp = *(const float2*)(sBias + ch * 64 + nt * 8 + cp);
                    acc[nt][0] += bp.x; acc[nt][1] += bp.y;
                    acc[nt][2] += bp.x; acc[nt][3] += bp.y;
                    r0[j] = fmaxf(r0[j], fmaxf(acc[nt][0], acc[nt][1]));
                    r1[j] = fmaxf(r1[j], fmaxf(acc[nt][2], acc[nt][3]));
                }
            }
        }
        float th0[3], th1[3];
        #pragma unroll
        for (int j = 0; j < 3; ++j) {
            float m0 = fmaxf(r0[j], __shfl_xor_sync(~0u, r0[j], 1));
            m0 = fmaxf(m0, __shfl_xor_sync(~0u, m0, 2));
            float m1 = fmaxf(r1[j], __shfl_xor_sync(~0u, r1[j], 1));
            m1 = fmaxf(m1, __shfl_xor_sync(~0u, m1, 2));
            th0[j] = m0 - 2.0f * tol0[j];
            th1[j] = m1 - 2.0f * tol1[j];
        }

        // ---- pass 2: recompute (bitwise identical), verify candidates ----
        float vb0[3], vb1[3]; int vi0[3], vi1[3];
        #pragma unroll
        for (int j = 0; j < 3; ++j) {
            vb0[j] = vb1[j] = -3.402823466e38f;
            vi0[j] = vi1[j] = 1 << 30;
        }
        for (int ch = 0; ch < 32; ++ch) {
            uint32_t b[4][4];
            #pragma unroll
            for (int bt = 0; bt < 4; ++bt)
                ldsm4(b[bt][0], b[bt][1], b[bt][2], b[bt][3],
                      sbase + (uint32_t)((ch * 64 + bt * 16 + bRow) * QPI + bKof));
            #pragma unroll
            for (int j = 0; j < 3; ++j) {
                float acc[8][4];
                #pragma unroll
                for (int nt = 0; nt < 8; ++nt)
                    mma16816z(acc[nt], a[j], b[nt>>1][(nt&1)*2], b[nt>>1][(nt&1)*2+1]);
                float m0 = -3.402823466e38f, m1 = -3.402823466e38f;
                #pragma unroll
                for (int nt = 0; nt < 8; ++nt) {
                    float2 bp = *(const float2*)(sBias + ch * 64 + nt * 8 + cp);
                    acc[nt][0] += bp.x; acc[nt][1] += bp.y;
                    acc[nt][2] += bp.x; acc[nt][3] += bp.y;
                    m0 = fmaxf(m0, fmaxf(acc[nt][0], acc[nt][1]));
                    m1 = fmaxf(m1, fmaxf(acc[nt][2], acc[nt][3]));
                }
                if (val[j] && (m0 >= th0[j] || m1 >= th1[j])) {
                    const int s0 = su[j] + lq, s1 = s0 + 8;
                    #pragma unroll
                    for (int nt = 0; nt < 8; ++nt) {
                        #pragma unroll
                        for (int e = 0; e < 2; ++e) {
                            const int c = ch * 64 + nt * 8 + cp + e;
                            if (acc[nt][e] >= th0[j]) {
                                float sc = exact_for(s0, c, U, Bm, rsU, rsB, cb);
                                if (sc > vb0[j] || (sc == vb0[j] && c < vi0[j]))
                                    { vb0[j] = sc; vi0[j] = c; }
                            }
                            if (acc[nt][2 + e] >= th1[j]) {
                                float sc = exact_for(s1, c, U, Bm, rsU, rsB, cb);
                                if (sc > vb1[j] || (sc == vb1[j] && c < vi1[j]))
                                    { vb1[j] = sc; vi1[j] = c; }
                            }
                        }
                    }
                }
            }
        }

        // ---- reduce (max score, min idx) over quad; stage ----
        #pragma unroll
        for (int j = 0; j < 3; ++j) {
            if (!val[j]) continue;
            #pragma unroll
            for (int off = 1; off < 4; off <<= 1) {
                float os = __shfl_xor_sync(~0u, vb0[j], off);
                int   oi = __shfl_xor_sync(~0u, vi0[j], off);
                if (os > vb0[j] || (os == vb0[j] && oi < vi0[j]))
                    { vb0[j] = os; vi0[j] = oi; }
                os = __shfl_xor_sync(~0u, vb1[j], off);
                oi = __shfl_xor_sync(~0u, vi1[j], off);
                if (os > vb1[j] || (os == vb1[j] && oi < vi1[j]))
                    { vb1[j] = os; vi1[j] = oi; }
            }
            if (lr == 0) {
                stage_row(su[j] + lq,     vi0[j], rsU, rsB, cb);
                stage_row(su[j] + lq + 8, vi1[j], rsU, rsB, cb);
            }
        }
    }
}

// ---------------------------------------------------------------------------
// GEMM (unchanged: 256 thr, warp tile 64x32, 112.9 us measured)
// ---------------------------------------------------------------------------
#define P_BY 400
#define A_SM_BYTES (128 * P_BY)
#define GEMM_SMEM  (2 * A_SM_BYTES)

__global__ __launch_bounds__(256) void gemm_mma_kernel(float* __restrict__ out)
{
    extern __shared__ __align__(16) unsigned char smem[];
    const int tid = threadIdx.x, wid = tid >> 5, lane = tid & 31;
    const int nb = blockIdx.x, mb = blockIdx.y;
    {
        const uint4* gA = (const uint4*)(g_Aext + (size_t)mb * 128 * KE);
        const uint4* gB = (const uint4*)(g_Bext + (size_t)nb * 128 * KE);
        #pragma unroll
        for (int it = 0; it < 12; ++it) {
            const int idx = tid + it * 256;
            const int r = idx / 24, j = idx % 24;
            *(uint4*)(smem + r * P_BY + j * 16)              = gA[idx];
            *(uint4*)(smem + A_SM_BYTES + r * P_BY + j * 16) = gB[idx];
        }
    }
    __syncthreads();
    const uint32_t sbase = smem_u32(smem);
    const int wm = wid >> 2, wn = wid & 3;
    const int aRow = lane & 15, aKof = (lane >> 4) * 16;
    const int g8 = lane >> 3;
    const int bRow = ((g8 & 2) ? 8 : 0) + (lane & 7), bKof = (g8 & 1) * 16;
    const uint32_t aAddr = sbase + (uint32_t)((wm * 64 + aRow) * P_BY + aKof);
    const uint32_t bAddr = sbase + A_SM_BYTES
                         + (uint32_t)((wn * 32 + bRow) * P_BY + bKof);
    float acc[4][4][4];
    #pragma unroll
    for (int i = 0; i < 4; ++i)
        #pragma unroll
        for (int j = 0; j < 4; ++j)
            #pragma unroll
            for (int e = 0; e < 4; ++e) acc[i][j][e] = 0.0f;
    #pragma unroll
    for (int ks = 0; ks < 12; ++ks) {
        const uint32_t kb = ks * 32;
        uint32_t a[4][4], b[2][4];
        #pragma unroll
        for (int mt = 0; mt < 4; ++mt)
            ldsm4(a[mt][0], a[mt][1], a[mt][2], a[mt][3], aAddr + mt * 16 * P_BY + kb);
        #pragma unroll
        for (int bt = 0; bt < 2; ++bt)
            ldsm4(b[bt][0], b[bt][1], b[bt][2], b[bt][3], bAddr + bt * 16 * P_BY + kb);
        #pragma unroll
        for (int mt = 0; mt < 4; ++mt)
            #pragma unroll
            for (int nt = 0; nt < 4; ++nt)
                mma16816(acc[mt][nt], a[mt],
                         b[nt >> 1][(nt & 1) * 2], b[nt >> 1][(nt & 1) * 2 + 1]);
    }
    const int r = lane >> 2, cp = (lane & 3) * 2;
    float* obase = out + (size_t)(mb * 128 + wm * 64) * N_COLS_B + nb * 128 + wn * 32;
    #pragma unroll
    for (int mt = 0; mt < 4; ++mt)
        #pragma unroll
        for (int nt = 0; nt < 4; ++nt) {
            float* o0 = obase + (size_t)(mt * 16 + r) * N_COLS_B + nt * 8 + cp;
            *(float2*)o0                  = make_float2(acc[mt][nt][0], acc[mt][nt][1]);
            *(float2*)(o0 + 8 * N_COLS_B) = make_float2(acc[mt][nt][2], acc[mt][nt][3]);
        }
}

extern "C" void kernel_launch(void* const* d_in, const int* in_sizes, int n_in,
                              void* d_out, int out_size)
{
    const float *U = nullptr, *B = nullptr, *rsU = nullptr, *rsB = nullptr, *cb = nullptr;
    for (int i = 0; i < n_in; ++i) {
        switch (in_sizes[i]) {
            case N_ROWS_U * RANK:  U   = (const float*)d_in[i]; break;
            case RANK * N_COLS_B:  B   = (const float*)d_in[i]; break;
            case N_ROWS_U:         rsU = (const float*)d_in[i]; break;
            case RANK:             rsB = (const float*)d_in[i]; break;
            case KCB * DS:         cb  = (const float*)d_in[i]; break;
            default: break;
        }
    }
    if (!U || !B || !rsU || !rsB || !cb) {
        U = (const float*)d_in[0]; B = (const float*)d_in[1];
        rsU = (const float*)d_in[2]; rsB = (const float*)d_in[3];
        cb = (const float*)d_in[4];
    }

    cudaFuncSetAttribute(score_kernel,
                         cudaFuncAttributeMaxDynamicSharedMemorySize, Q_SMEM);
    cudaFuncSetAttribute(gemm_mma_kernel,
                         cudaFuncAttributeMaxDynamicSharedMemorySize, GEMM_SMEM);

    prep_cb<<<KCB / 128, 128>>>(cb);
    prep_g<<<TOTAL_SUBS / 128, 128>>>(U, B, rsU, rsB);
    score_kernel<<<148, 384, Q_SMEM>>>(U, B, rsU, rsB, cb);
    gemm_mma_kernel<<<dim3(N_COLS_B / 128, N_ROWS_U / 128), 256, GEMM_SMEM>>>((float*)d_out);
}

// round 15
// speedup vs baseline: 1.4615x; 1.4615x over previous
#include <cuda_runtime.h>
#include <cuda_bf16.h>
#include <cstdint>

#define N_ROWS_U 16384
#define RANK     64
#define N_COLS_B 4096
#define KCB      2048
#define DS       16
#define SUBS_U   65536
#define SUBS_B   16384
#define TOTAL_SUBS 81920
#define KE 192
#define QPI 48                        // scoring C smem pitch (bytes)

__device__ __align__(16) unsigned short g_Aext[(size_t)N_ROWS_U * KE];
__device__ __align__(16) unsigned short g_Bext[(size_t)N_COLS_B * KE];
__device__ __align__(16) unsigned short g_Ghi [(size_t)TOTAL_SUBS * 16]; // hi only
__device__ __align__(16) unsigned short g_Chi [(size_t)KCB * 16];        // hi only
__device__ float g_CbBias[KCB];

// ---- exact fp32 chains (selection identity; unchanged since R7) ----
__device__ __forceinline__ float bias_of(const float* row) {
    float n = row[0] * row[0];
    #pragma unroll
    for (int i = 1; i < DS; ++i) n = fmaf(row[i], row[i], n);
    return -0.5f * n;
}
__device__ __forceinline__ float score_of(const float* g, const float* row, float bias) {
    float A = bias, B = 0.0f;
    #pragma unroll
    for (int j = 0; j < 8; ++j) {
        A = fmaf(g[2 * j],     row[2 * j],     A);
        B = fmaf(g[2 * j + 1], row[2 * j + 1], B);
    }
    return A + B;
}
__device__ __noinline__ float exact_score(const float* W, float inv, const float* cbrow) {
    float g[DS];
    const float4* w4 = (const float4*)W;
    #pragma unroll
    for (int q = 0; q < 4; ++q) {
        float4 v = w4[q];
        g[4*q+0] = v.x * inv; g[4*q+1] = v.y * inv;
        g[4*q+2] = v.z * inv; g[4*q+3] = v.w * inv;
    }
    return score_of(g, cbrow, bias_of(cbrow));
}

__device__ __forceinline__ uint32_t smem_u32(const void* p) {
    uint32_t a;
    asm("{ .reg .u64 t; cvta.to.shared.u64 t, %1; cvt.u32.u64 %0, t; }"
        : "=r"(a) : "l"(p));
    return a;
}
__device__ __forceinline__ void ldsm4(uint32_t& r0, uint32_t& r1,
                                      uint32_t& r2, uint32_t& r3, uint32_t addr) {
    asm volatile("ldmatrix.sync.aligned.m8n8.x4.shared.b16 {%0,%1,%2,%3}, [%4];"
                 : "=r"(r0), "=r"(r1), "=r"(r2), "=r"(r3) : "r"(addr));
}
__device__ __forceinline__ void mma16816(float* c, const uint32_t* a,
                                         uint32_t b0, uint32_t b1) {
    asm("mma.sync.aligned.m16n8k16.row.col.f32.bf16.bf16.f32 "
        "{%0,%1,%2,%3}, {%4,%5,%6,%7}, {%8,%9}, {%0,%1,%2,%3};"
        : "+f"(c[0]), "+f"(c[1]), "+f"(c[2]), "+f"(c[3])
        : "r"(a[0]), "r"(a[1]), "r"(a[2]), "r"(a[3]), "r"(b0), "r"(b1));
}
__device__ __forceinline__ void mma16816z(float* c, const uint32_t* a,
                                          uint32_t b0, uint32_t b1) {
    float z = 0.0f;
    asm("mma.sync.aligned.m16n8k16.row.col.f32.bf16.bf16.f32 "
        "{%0,%1,%2,%3}, {%4,%5,%6,%7}, {%8,%9}, {%10,%11,%12,%13};"
        : "=f"(c[0]), "=f"(c[1]), "=f"(c[2]), "=f"(c[3])
        : "r"(a[0]), "r"(a[1]), "r"(a[2]), "r"(a[3]), "r"(b0), "r"(b1),
          "f"(z), "f"(z), "f"(z), "f"(z));
}

// ---- prep: codebook bf16 hi image + fp32 bias ----
__global__ __launch_bounds__(128) void prep_cb(const float* __restrict__ cb) {
    const int c = blockIdx.x * 128 + threadIdx.x;
    float row[DS];
    const float4* r4 = (const float4*)(cb + (size_t)c * DS);
    #pragma unroll
    for (int q = 0; q < 4; ++q) {
        float4 v = r4[q];
        row[4*q] = v.x; row[4*q+1] = v.y; row[4*q+2] = v.z; row[4*q+3] = v.w;
    }
    g_CbBias[c] = bias_of(row);
    unsigned short* o = g_Chi + (size_t)c * 16;
    #pragma unroll
    for (int i = 0; i < DS; ++i)
        o[i] = __bfloat16_as_ushort(__float2bfloat16(row[i]));
}

// ---- prep: subvector bf16 hi image ----
__global__ __launch_bounds__(128) void prep_g(
    const float* __restrict__ U, const float* __restrict__ Bm,
    const float* __restrict__ rsU, const float* __restrict__ rsB)
{
    const int s = blockIdx.x * 128 + threadIdx.x;
    const float* W; float rsv;
    if (s < SUBS_U) { W = U + (size_t)s * DS; rsv = rsU[s >> 2]; }
    else { int s2 = s - SUBS_U; W = Bm + (size_t)s2 * DS; rsv = rsB[s2 >> 8]; }
    const float inv = 1.0f / rsv;
    unsigned short* o = g_Ghi + (size_t)s * 16;
    const float4* w4 = (const float4*)W;
    #pragma unroll
    for (int q = 0; q < 4; ++q) {
        float4 v = w4[q];
        float gg[4] = {v.x * inv, v.y * inv, v.z * inv, v.w * inv};
        #pragma unroll
        for (int e = 0; e < 4; ++e)
            o[4*q + e] = __bfloat16_as_ushort(__float2bfloat16(gg[e]));
    }
}

// ---- staging of one selected codeword into GEMM operands ----
__device__ __noinline__ void stage_row(int s, int bidx, float rsv,
                                       const float* __restrict__ cb) {
    float cw[DS];
    const float4* c4 = (const float4*)(cb + (size_t)bidx * DS);
    #pragma unroll
    for (int q = 0; q < 4; ++q) {
        float4 v = c4[q];
        cw[4*q+0] = v.x * rsv; cw[4*q+1] = v.y * rsv;
        cw[4*q+2] = v.z * rsv; cw[4*q+3] = v.w * rsv;
    }
    if (s < SUBS_U) {
        const int m = s >> 2, kk0 = (s & 3) << 4;
        unsigned short* rowp = g_Aext + (size_t)m * KE;
        #pragma unroll
        for (int e = 0; e < 8; ++e) {
            const int k = kk0 + 2 * e;
            float x0 = cw[2*e], x1 = cw[2*e+1];
            __nv_bfloat16 h0 = __float2bfloat16(x0), h1 = __float2bfloat16(x1);
            __nv_bfloat16 l0 = __float2bfloat16(x0 - __bfloat162float(h0));
            __nv_bfloat16 l1 = __float2bfloat16(x1 - __bfloat162float(h1));
            unsigned hp = (unsigned)__bfloat16_as_ushort(h0)
                        | ((unsigned)__bfloat16_as_ushort(h1) << 16);
            unsigned lp = (unsigned)__bfloat16_as_ushort(l0)
                        | ((unsigned)__bfloat16_as_ushort(l1) << 16);
            *(unsigned*)(rowp + k)       = hp;
            *(unsigned*)(rowp + 64 + k)  = lp;
            *(unsigned*)(rowp + 128 + k) = hp;
        }
    } else {
        const int s2 = s - SUBS_U, kB = s2 >> 8, n0g = (s2 & 255) << 4;
        #pragma unroll
        for (int i = 0; i < DS; ++i) {
            unsigned short* rowp = g_Bext + (size_t)(n0g + i) * KE;
            float x = cw[i];
            __nv_bfloat16 h = __float2bfloat16(x);
            __nv_bfloat16 l = __float2bfloat16(x - __bfloat162float(h));
            rowp[kB]       = __bfloat16_as_ushort(h);
            rowp[64 + kB]  = __bfloat16_as_ushort(h);
            rowp[128 + kB] = __bfloat16_as_ushort(l);
        }
    }
}

// ---- HMMA chunk: 64 codeword cols, K=16 one-sided, acc[nt][4] fp32 ----
__device__ __forceinline__ void score_chunk(float acc[8][4], const uint32_t a[4],
                                            uint32_t sbase, int ch, int bRow, int bKof)
{
    uint32_t b[4][4];
    #pragma unroll
    for (int bt = 0; bt < 4; ++bt)
        ldsm4(b[bt][0], b[bt][1], b[bt][2], b[bt][3],
              sbase + (uint32_t)((ch * 64 + bt * 16 + bRow) * QPI + bKof));
    #pragma unroll
    for (int nt = 0; nt < 8; ++nt)
        mma16816z(acc[nt], a, b[nt>>1][(nt&1)*2], b[nt>>1][(nt&1)*2+1]);
}

#define Q_CB (KCB * QPI)              // 98304
#define Q_SMEM (Q_CB + KCB * 4)       // 106496

__global__ __launch_bounds__(384) void score_kernel(
    const float* __restrict__ U, const float* __restrict__ Bm,
    const float* __restrict__ rsU, const float* __restrict__ rsB,
    const float* __restrict__ cb)
{
    extern __shared__ __align__(16) unsigned char qsm[];
    float* sBias = (float*)(qsm + Q_CB);
    const int tid = threadIdx.x, wid = tid >> 5, lane = tid & 31;

    {   // stage resident C (2048 rows x 2 uint4, pitch 48) + bias
        const uint4* src = (const uint4*)g_Chi;
        for (int idx = tid; idx < KCB * 2; idx += 384) {
            const int r = idx >> 1, j = idx & 1;
            *(uint4*)(qsm + r * QPI + j * 16) = src[idx];
        }
        for (int c = tid; c < KCB; c += 384) sBias[c] = g_CbBias[c];
    }
    __syncthreads();

    const uint32_t sbase = smem_u32(qsm);
    const int g8 = lane >> 3;
    const int bRow = ((g8 & 2) ? 8 : 0) + (lane & 7);
    const int bKof = (g8 & 1) * 16;
    const int lr = lane & 3, cp = lr * 2;

    for (int unit = blockIdx.x * 12 + wid; unit < TOTAL_SUBS / 16; unit += 148 * 12) {
        const int s0 = unit * 16 + (lane >> 2), s1 = s0 + 8;

        // per-row context
        const float *W0, *W1; float rs0, rs1;
        if (s0 < SUBS_U) { W0 = U + (size_t)s0 * DS; rs0 = rsU[s0 >> 2]; }
        else { int t = s0 - SUBS_U; W0 = Bm + (size_t)t * DS; rs0 = rsB[t >> 8]; }
        if (s1 < SUBS_U) { W1 = U + (size_t)s1 * DS; rs1 = rsU[s1 >> 2]; }
        else { int t = s1 - SUBS_U; W1 = Bm + (size_t)t * DS; rs1 = rsB[t >> 8]; }
        const float in0 = 1.0f / rs0, in1 = 1.0f / rs1;

        float gn0 = 0.0f, gn1 = 0.0f;
        #pragma unroll
        for (int i = 0; i < DS; ++i) {
            float a0 = W0[i] * in0, a1 = W1[i] * in1;
            gn0 = fmaf(a0, a0, gn0); gn1 = fmaf(a1, a1, gn1);
        }
        // one-sided bf16 rank error <= 2^-8*||g||*||c|| <= 5.9e-4*||g||;
        // tol gives >4x margin.
        const float tol0 = 2.5e-3f * sqrtf(gn0), tol1 = 2.5e-3f * sqrtf(gn1);

        // A frags (hi) from g_Ghi (row-major 8 u32 per row)
        uint32_t a[4];
        {
            const unsigned* G = (const unsigned*)g_Ghi;
            a[0] = G[(size_t)s0 * 8 + lr];
            a[1] = G[(size_t)s1 * 8 + lr];
            a[2] = G[(size_t)s0 * 8 + 4 + lr];
            a[3] = G[(size_t)s1 * 8 + 4 + lr];
        }

        // ---- pass 1: ranked row maxima ----
        float r0 = -3.402823466e38f, r1 = -3.402823466e38f;
        for (int ch = 0; ch < 32; ++ch) {
            float acc[8][4];
            score_chunk(acc, a, sbase, ch, bRow, bKof);
            #pragma unroll
            for (int nt = 0; nt < 8; ++nt) {
                float2 bp = *(const float2*)(sBias + ch * 64 + nt * 8 + cp);
                r0 = fmaxf(r0, fmaxf(acc[nt][0] + bp.x, acc[nt][1] + bp.y));
                r1 = fmaxf(r1, fmaxf(acc[nt][2] + bp.x, acc[nt][3] + bp.y));
            }
        }
        r0 = fmaxf(r0, __shfl_xor_sync(~0u, r0, 1));
        r0 = fmaxf(r0, __shfl_xor_sync(~0u, r0, 2));
        r1 = fmaxf(r1, __shfl_xor_sync(~0u, r1, 1));
        r1 = fmaxf(r1, __shfl_xor_sync(~0u, r1, 2));
        const float th0 = r0 - 2.0f * tol0, th1 = r1 - 2.0f * tol1;

        // ---- pass 2: recompute (bitwise identical), verify candidates ----
        float vb0 = -3.402823466e38f, vb1 = -3.402823466e38f;
        int vi0 = 1 << 30, vi1 = 1 << 30;
        for (int ch = 0; ch < 32; ++ch) {
            float acc[8][4];
            score_chunk(acc, a, sbase, ch, bRow, bKof);
            #pragma unroll
            for (int nt = 0; nt < 8; ++nt) {
                float2 bp = *(const float2*)(sBias + ch * 64 + nt * 8 + cp);
                const int cbase = ch * 64 + nt * 8 + cp;
                #pragma unroll
                for (int e = 0; e < 2; ++e) {
                    float bb = e ? bp.y : bp.x;
                    if (acc[nt][e] + bb >= th0) {
                        const int c = cbase + e;
                        float sc = exact_score(W0, in0, cb + (size_t)c * DS);
                        if (sc > vb0 || (sc == vb0 && c < vi0)) { vb0 = sc; vi0 = c; }
                    }
                    if (acc[nt][2 + e] + bb >= th1) {
                        const int c = cbase + e;
                        float sc = exact_score(W1, in1, cb + (size_t)c * DS);
                        if (sc > vb1 || (sc == vb1 && c < vi1)) { vb1 = sc; vi1 = c; }
                    }
                }
            }
        }
        // reduce (max score, min index) across the 4 lanes of each row
        #pragma unroll
        for (int off = 1; off < 4; off <<= 1) {
            float os = __shfl_xor_sync(~0u, vb0, off);
            int   oi = __shfl_xor_sync(~0u, vi0, off);
            if (os > vb0 || (os == vb0 && oi < vi0)) { vb0 = os; vi0 = oi; }
            os = __shfl_xor_sync(~0u, vb1, off);
            oi = __shfl_xor_sync(~0u, vi1, off);
            if (os > vb1 || (os == vb1 && oi < vi1)) { vb1 = os; vi1 = oi; }
        }
        if (lr == 0) {
            stage_row(s0, vi0, rs0, cb);
            stage_row(s1, vi1, rs1, cb);
        }
    }
}

// ---------------------------------------------------------------------------
// GEMM (unchanged: 256 thr, warp tile 64x32, 112.9 us measured)
// ---------------------------------------------------------------------------
#define P_BY 400
#define A_SM_BYTES (128 * P_BY)
#define GEMM_SMEM  (2 * A_SM_BYTES)

__global__ __launch_bounds__(256) void gemm_mma_kernel(float* __restrict__ out)
{
    extern __shared__ __align__(16) unsigned char smem[];
    const int tid = threadIdx.x, wid = tid >> 5, lane = tid & 31;
    const int nb = blockIdx.x, mb = blockIdx.y;
    {
        const uint4* gA = (const uint4*)(g_Aext + (size_t)mb * 128 * KE);
        const uint4* gB = (const uint4*)(g_Bext + (size_t)nb * 128 * KE);
        #pragma unroll
        for (int it = 0; it < 12; ++it) {
            const int idx = tid + it * 256;
            const int r = idx / 24, j = idx % 24;
            *(uint4*)(smem + r * P_BY + j * 16)              = gA[idx];
            *(uint4*)(smem + A_SM_BYTES + r * P_BY + j * 16) = gB[idx];
        }
    }
    __syncthreads();
    const uint32_t sbase = smem_u32(smem);
    const int wm = wid >> 2, wn = wid & 3;
    const int aRow = lane & 15, aKof = (lane >> 4) * 16;
    const int g8 = lane >> 3;
    const int bRow = ((g8 & 2) ? 8 : 0) + (lane & 7), bKof = (g8 & 1) * 16;
    const uint32_t aAddr = sbase + (uint32_t)((wm * 64 + aRow) * P_BY + aKof);
    const uint32_t bAddr = sbase + A_SM_BYTES
                         + (uint32_t)((wn * 32 + bRow) * P_BY + bKof);
    float acc[4][4][4];
    #pragma unroll
    for (int i = 0; i < 4; ++i)
        #pragma unroll
        for (int j = 0; j < 4; ++j)
            #pragma unroll
            for (int e = 0; e < 4; ++e) acc[i][j][e] = 0.0f;
    #pragma unroll
    for (int ks = 0; ks < 12; ++ks) {
        const uint32_t kb = ks * 32;
        uint32_t a[4][4], b[2][4];
        #pragma unroll
        for (int mt = 0; mt < 4; ++mt)
            ldsm4(a[mt][0], a[mt][1], a[mt][2], a[mt][3], aAddr + mt * 16 * P_BY + kb);
        #pragma unroll
        for (int bt = 0; bt < 2; ++bt)
            ldsm4(b[bt][0], b[bt][1], b[bt][2], b[bt][3], bAddr + bt * 16 * P_BY + kb);
        #pragma unroll
        for (int mt = 0; mt < 4; ++mt)
            #pragma unroll
            for (int nt = 0; nt < 4; ++nt)
                mma16816(acc[mt][nt], a[mt],
                         b[nt >> 1][(nt & 1) * 2], b[nt >> 1][(nt & 1) * 2 + 1]);
    }
    const int r = lane >> 2, cp = (lane & 3) * 2;
    float* obase = out + (size_t)(mb * 128 + wm * 64) * N_COLS_B + nb * 128 + wn * 32;
    #pragma unroll
    for (int mt = 0; mt < 4; ++mt)
        #pragma unroll
        for (int nt = 0; nt < 4; ++nt) {
            float* o0 = obase + (size_t)(mt * 16 + r) * N_COLS_B + nt * 8 + cp;
            *(float2*)o0                  = make_float2(acc[mt][nt][0], acc[mt][nt][1]);
            *(float2*)(o0 + 8 * N_COLS_B) = make_float2(acc[mt][nt][2], acc[mt][nt][3]);
        }
}

extern "C" void kernel_launch(void* const* d_in, const int* in_sizes, int n_in,
                              void* d_out, int out_size)
{
    const float *U = nullptr, *B = nullptr, *rsU = nullptr, *rsB = nullptr, *cb = nullptr;
    for (int i = 0; i < n_in; ++i) {
        switch (in_sizes[i]) {
            case N_ROWS_U * RANK:  U   = (const float*)d_in[i]; break;
            case RANK * N_COLS_B:  B   = (const float*)d_in[i]; break;
            case N_ROWS_U:         rsU = (const float*)d_in[i]; break;
            case RANK:             rsB = (const float*)d_in[i]; break;
            case KCB * DS:         cb  = (const float*)d_in[i]; break;
            default: break;
        }
    }
    if (!U || !B || !rsU || !rsB || !cb) {
        U = (const float*)d_in[0]; B = (const float*)d_in[1];
        rsU = (const float*)d_in[2]; rsB = (const float*)d_in[3];
        cb = (const float*)d_in[4];
    }

    cudaFuncSetAttribute(score_kernel,
                         cudaFuncAttributeMaxDynamicSharedMemorySize, Q_SMEM);
    cudaFuncSetAttribute(gemm_mma_kernel,
                         cudaFuncAttributeMaxDynamicSharedMemorySize, GEMM_SMEM);

    prep_cb<<<KCB / 128, 128>>>(cb);
    prep_g<<<TOTAL_SUBS / 128, 128>>>(U, B, rsU, rsB);
    score_kernel<<<148, 384, Q_SMEM>>>(U, B, rsU, rsB, cb);
    gemm_mma_kernel<<<dim3(N_COLS_B / 128, N_ROWS_U / 128), 256, GEMM_SMEM>>>((float*)d_out);
}